// round 7
// baseline (speedup 1.0000x reference)
#include <cuda_runtime.h>
#include <cuda_bf16.h>

typedef unsigned int u32;

// B=2, H=16, L=S=2048, E=D=64
// inputs: d_in[2]=values [B,S,H,D], d_in[3]=scores [B,H,L,S]; out [B,L,H,D] f32.
// Math: w=softmax(scores,-1); causal mask; A=softmax(w,-1); out=A@V.
//  * scores~N(0,1): first softmax safe without max subtraction.
//  * w in (0,1]: second softmax safe without max subtraction.
// K1: Z1[row]=sum exp(s).
// K2: warp-specialized pipeline. Producers (warps 8-15): e=exp(exp(s)/Z1)
//     (causal), bf16 hi/lo split, STS into double-buffered stages; Z2 in regs.
//     Consumers (warps 0-7): mma.sync m16n8k16 bf16, 3 combos
//     (Ehi*Vhi + Elo*Vhi + Ehi*Vlo). out = D/Z2.
// Named barriers: FULL[b]=1+b, EMPTY[b]=3+b, count=512 (256 arrive + 256 sync).

#define NROWS (2 * 16 * 2048)
__device__ float g_z1[NROWS];

#define PITCH 72                       // bf16/row (144B, conflict-free)
#define A_LO_OFF 18432                 // 128*72*2
#define V_HI_OFF 36864                 // A hi+lo
#define V_LO_OFF 46080                 // + 64*72*2
#define STAGE    55296                 // + 64*72*2
#define SMEM_TOT (2 * STAGE)           // 110592

__device__ __forceinline__ u32 smem_u32(const void* p) {
    u32 a;
    asm("{ .reg .u64 t; cvta.to.shared.u64 t, %1; cvt.u32.u64 %0, t; }" : "=r"(a) : "l"(p));
    return a;
}
__device__ __forceinline__ void ldsm_x4(u32* r, u32 a) {
    asm volatile("ldmatrix.sync.aligned.m8n8.x4.shared.b16 {%0,%1,%2,%3}, [%4];"
                 : "=r"(r[0]), "=r"(r[1]), "=r"(r[2]), "=r"(r[3]) : "r"(a));
}
__device__ __forceinline__ void ldsm_x4t(u32* r, u32 a) {
    asm volatile("ldmatrix.sync.aligned.m8n8.x4.trans.shared.b16 {%0,%1,%2,%3}, [%4];"
                 : "=r"(r[0]), "=r"(r[1]), "=r"(r[2]), "=r"(r[3]) : "r"(a));
}
__device__ __forceinline__ void mma16816(float* d, const u32* a, u32 b0, u32 b1) {
    asm volatile(
        "mma.sync.aligned.m16n8k16.row.col.f32.bf16.bf16.f32 "
        "{%0,%1,%2,%3}, {%4,%5,%6,%7}, {%8,%9}, {%0,%1,%2,%3};"
        : "+f"(d[0]), "+f"(d[1]), "+f"(d[2]), "+f"(d[3])
        : "r"(a[0]), "r"(a[1]), "r"(a[2]), "r"(a[3]), "r"(b0), "r"(b1));
}
__device__ __forceinline__ void pack_pair(float e0, float e1, u32& hi, u32& lo) {
    __nv_bfloat162 hh = __floats2bfloat162_rn(e0, e1);
    hi = *reinterpret_cast<u32*>(&hh);
    __nv_bfloat162 ll = __floats2bfloat162_rn(e0 - __bfloat162float(hh.x),
                                              e1 - __bfloat162float(hh.y));
    lo = *reinterpret_cast<u32*>(&ll);
}
#define BAR_SYNC(id)   asm volatile("bar.sync %0, 512;"   :: "r"(id) : "memory")
#define BAR_ARRIVE(id) asm volatile("bar.arrive %0, 512;" :: "r"(id) : "memory")

// ---------------------------------------------------------------------------
// K1: per-row sum of exp(scores). HBM-roofline stream (512 MB, ~95% of spec).
// ---------------------------------------------------------------------------
__global__ void __launch_bounds__(256) k_rowsum(const float* __restrict__ scores) {
    int row  = blockIdx.x * 8 + threadIdx.y;
    int lane = threadIdx.x;
    const float4* p = (const float4*)(scores + (size_t)row * 2048);
    float z = 0.f;
#pragma unroll
    for (int i = 0; i < 16; i++) {
        float4 v = __ldcs(p + lane + i * 32);
        z += __expf(v.x) + __expf(v.y) + __expf(v.z) + __expf(v.w);
    }
#pragma unroll
    for (int o = 16; o; o >>= 1) z += __shfl_xor_sync(0xffffffffu, z, o);
    if (lane == 0) g_z1[row] = z;
}

// ---------------------------------------------------------------------------
// K2: warp-specialized causal second-softmax + AV on tensor cores.
// Grid (16, 32), 512 threads. l-tile 128, s-tile 64, 2-stage smem pipeline.
// ---------------------------------------------------------------------------
__global__ void __launch_bounds__(512, 1)
k_attn4(const float* __restrict__ scores,
        const float* __restrict__ values,
        float* __restrict__ out) {
    extern __shared__ __align__(16) char sm[];
    __shared__ float z2_s[128];

    const u32 smb = smem_u32(sm);
    int tid = threadIdx.x, wid = tid >> 5, lane = tid & 31;
    int bh = blockIdx.y, b = bh >> 4, h = bh & 15;
    int l0 = (15 - (int)blockIdx.x) * 128;   // heavy tiles first
    int T  = (l0 + 128) >> 6;                // s-tiles (2..32)

    if (wid >= 8) {
        // ================= PRODUCER (warps 8-15, 256 threads) =================
        int t  = tid - 256;
        int r  = t >> 1;                     // local row 0..127
        int c0 = (t & 1) * 32;               // 32-col half of s-tile
        int l  = l0 + r;
        float rz1 = 1.0f / g_z1[bh * 2048 + l];
        const float* srow = scores + ((size_t)bh * 2048 + l) * 2048;
        int vj = t >> 2, vq = (t & 3) * 16;
        const float* vrow = values + (size_t)b * 2048 * 1024 + h * 64 + vq;
        const u32 aOff = (u32)(r * PITCH + c0) * 2;
        const u32 vOff = V_HI_OFF + (u32)(vj * PITCH + vq) * 2;
        float z2 = 0.f;

        for (int i = 0; i < T; i++) {
            int s0 = i * 64;
            // ---- gmem loads (overlap consumers' MMA of tile i-1) ----
            float4 vv[4];
            const float4* vg = (const float4*)(vrow + (size_t)(s0 + vj) * 1024);
#pragma unroll
            for (int q = 0; q < 4; q++) vv[q] = __ldg(vg + q);

            uint4 ahiR[4], aloR[4];
            if (s0 + c0 <= l) {
                const float4* spp = (const float4*)(srow + s0 + c0);
                float4 s4[8];
#pragma unroll
                for (int g = 0; g < 8; g++) s4[g] = __ldcs(spp + g);
                const float* sf = (const float*)s4;
#pragma unroll
                for (int g = 0; g < 4; g++) {
                    u32 hp[4], lp[4];
#pragma unroll
                    for (int p = 0; p < 4; p++) {
                        int idx = g * 8 + 2 * p;
                        int j = s0 + c0 + idx;
                        float e0 = (j     <= l) ? __expf(__expf(sf[idx])     * rz1) : 0.f;
                        float e1 = (j + 1 <= l) ? __expf(__expf(sf[idx + 1]) * rz1) : 0.f;
                        z2 += e0 + e1;
                        pack_pair(e0, e1, hp[p], lp[p]);
                    }
                    ahiR[g] = make_uint4(hp[0], hp[1], hp[2], hp[3]);
                    aloR[g] = make_uint4(lp[0], lp[1], lp[2], lp[3]);
                }
            } else {
#pragma unroll
                for (int g = 0; g < 4; g++) {
                    ahiR[g] = make_uint4(0, 0, 0, 0);
                    aloR[g] = make_uint4(0, 0, 0, 0);
                }
            }
            uint4 vhiR[2], vloR[2];
            {
                const float* f = (const float*)vv;
#pragma unroll
                for (int g = 0; g < 2; g++) {
                    u32 hp[4], lp[4];
#pragma unroll
                    for (int p = 0; p < 4; p++)
                        pack_pair(f[g * 8 + 2 * p], f[g * 8 + 2 * p + 1], hp[p], lp[p]);
                    vhiR[g] = make_uint4(hp[0], hp[1], hp[2], hp[3]);
                    vloR[g] = make_uint4(lp[0], lp[1], lp[2], lp[3]);
                }
            }

            // ---- wait stage free (consumers done with tile i-2), fill, signal ----
            if (i >= 2) BAR_SYNC(3 + (i & 1));
            char* buf = sm + (i & 1) * STAGE;
#pragma unroll
            for (int g = 0; g < 4; g++) {
                *(uint4*)(buf + aOff + 16 * g)            = ahiR[g];
                *(uint4*)(buf + aOff + A_LO_OFF + 16 * g) = aloR[g];
            }
#pragma unroll
            for (int g = 0; g < 2; g++) {
                *(uint4*)(buf + vOff + 16 * g)                        = vhiR[g];
                *(uint4*)(buf + vOff + (V_LO_OFF - V_HI_OFF) + 16 * g) = vloR[g];
            }
            BAR_ARRIVE(1 + (i & 1));
        }
        // Z2 delivery (two threads per row)
        z2 += __shfl_xor_sync(0xffffffffu, z2, 1);
        if (!(t & 1)) z2_s[r] = z2;
    } else {
        // ================= CONSUMER (warps 0-7) =================
        // warp = (strip-pair sp: rows 32sp..32sp+31) x (n-half nh: cols 32nh..+31)
        int sp = wid & 3, nh = wid >> 2;
        int rowTop = l0 + 32 * sp + 31;
        const u32 aLd0 = (u32)(((32 * sp + (lane & 15)) * PITCH + 8 * (lane >> 4)) * 2);
        const u32 aLd1 = aLd0 + 16 * PITCH * 2;
        const u32 bLdB = V_HI_OFF + (u32)(((lane & 15) * PITCH + 8 * (lane >> 4)) * 2)
                       + (u32)(2 * nh) * 32;

        float acc[8][4];
#pragma unroll
        for (int n = 0; n < 8; n++)
#pragma unroll
            for (int q = 0; q < 4; q++) acc[n][q] = 0.f;

        for (int i = 0; i < T; i++) {
            int s0 = i * 64;
            BAR_SYNC(1 + (i & 1));
            if (s0 <= rowTop) {                 // skip fully-masked strip pairs
                u32 base = smb + (i & 1) * STAGE;
#pragma unroll
                for (int k = 0; k < 4; k++) {
                    u32 ah0[4], al0[4], ah1[4], al1[4];
                    ldsm_x4(ah0, base + aLd0 + k * 32);
                    ldsm_x4(al0, base + aLd0 + A_LO_OFF + k * 32);
                    ldsm_x4(ah1, base + aLd1 + k * 32);
                    ldsm_x4(al1, base + aLd1 + A_LO_OFF + k * 32);
#pragma unroll
                    for (int tt = 0; tt < 2; tt++) {
                        u32 bh4[4], bl4[4];
                        u32 ba = base + bLdB + (u32)(k * 16 * PITCH * 2) + tt * 32;
                        ldsm_x4t(bh4, ba);
                        ldsm_x4t(bl4, ba + (V_LO_OFF - V_HI_OFF));
                        mma16816(acc[2 * tt],     ah0, bh4[0], bh4[1]);
                        mma16816(acc[2 * tt],     al0, bh4[0], bh4[1]);
                        mma16816(acc[2 * tt],     ah0, bl4[0], bl4[1]);
                        mma16816(acc[2 * tt + 1], ah0, bh4[2], bh4[3]);
                        mma16816(acc[2 * tt + 1], al0, bh4[2], bh4[3]);
                        mma16816(acc[2 * tt + 1], ah0, bl4[2], bl4[3]);
                        mma16816(acc[4 + 2 * tt],     ah1, bh4[0], bh4[1]);
                        mma16816(acc[4 + 2 * tt],     al1, bh4[0], bh4[1]);
                        mma16816(acc[4 + 2 * tt],     ah1, bl4[0], bl4[1]);
                        mma16816(acc[4 + 2 * tt + 1], ah1, bh4[2], bh4[3]);
                        mma16816(acc[4 + 2 * tt + 1], al1, bh4[2], bh4[3]);
                        mma16816(acc[4 + 2 * tt + 1], ah1, bl4[2], bl4[3]);
                    }
                }
            }
            BAR_ARRIVE(3 + (i & 1));
        }

        __syncthreads();                        // z2_s ready
        // ---- epilogue: scale by 1/Z2, store [B,L,H,D] ----
#pragma unroll
        for (int s = 0; s < 2; s++) {
            int rl = 32 * sp + 16 * s + (lane >> 2);
            float rza = 1.0f / z2_s[rl];
            float rzb = 1.0f / z2_s[rl + 8];
            float* o0 = out + (((size_t)b * 2048 + l0 + rl) * 16 + h) * 64
                      + 32 * nh + 2 * (lane & 3);
            float* o1 = o0 + 8 * 16 * 64;
#pragma unroll
            for (int n = 0; n < 4; n++) {
                *(float2*)(o0 + 8 * n) = make_float2(acc[s * 4 + n][0] * rza,
                                                     acc[s * 4 + n][1] * rza);
                *(float2*)(o1 + 8 * n) = make_float2(acc[s * 4 + n][2] * rzb,
                                                     acc[s * 4 + n][3] * rzb);
            }
        }
        return;
    }
    __syncthreads();                            // producers match consumers' barrier
}

// ---------------------------------------------------------------------------
extern "C" void kernel_launch(void* const* d_in, const int* in_sizes, int n_in,
                              void* d_out, int out_size) {
    (void)in_sizes; (void)n_in; (void)out_size;
    const float* values = (const float*)d_in[2];
    const float* scores = (const float*)d_in[3];
    float* out = (float*)d_out;

    static int attr_done = 0;
    if (!attr_done) {
        cudaFuncSetAttribute(k_attn4, cudaFuncAttributeMaxDynamicSharedMemorySize, SMEM_TOT);
        attr_done = 1;
    }

    k_rowsum<<<dim3(NROWS / 8), dim3(32, 8)>>>(scores);
    k_attn4<<<dim3(16, 32), 512, SMEM_TOT>>>(scores, values, out);
}

// round 9
// speedup vs baseline: 1.5991x; 1.5991x over previous
#include <cuda_runtime.h>
#include <cuda_fp16.h>

typedef unsigned int u32;

// B=2, H=16, L=S=2048, E=D=64
// inputs: d_in[2]=values [B,S,H,D], d_in[3]=scores [B,H,L,S]; out [B,L,H,D] f32.
// Math: w=softmax(scores,-1); causal mask; A=softmax(w,-1); out=A@V.
//  * scores~N(0,1): first softmax safe without max subtraction.
//  * w in (0,1]: second softmax safe without max subtraction.
// K1: Z1[row]=sum exp(s).
// K2: e=exp(exp(s)/Z1) (causal), Z2=sum e (exact f32),
//     D = E @ V via single-combo fp16 mma.sync m16n8k16 (e in [0,e] fits fp16
//     with ~2^-11 rel err; norm-level output err ~3e-4 << 1e-3), out = D/Z2.
// Software pipeline: double-buffered smem, LDG(i+1) issued before MMA(i).

#define NROWS (2 * 16 * 2048)
__device__ float g_z1[NROWS];

#define PITCH 72                       // fp16/row (144B, ldsm conflict-free)
#define V_OFF 18432                    // 128*72*2
#define STAGE 27648                    // + 64*72*2
#define SMEM_TOT (2 * STAGE)           // 55296

__device__ __forceinline__ u32 smem_u32(const void* p) {
    u32 a;
    asm("{ .reg .u64 t; cvta.to.shared.u64 t, %1; cvt.u32.u64 %0, t; }" : "=r"(a) : "l"(p));
    return a;
}
__device__ __forceinline__ void ldsm_x4(u32* r, u32 a) {
    asm volatile("ldmatrix.sync.aligned.m8n8.x4.shared.b16 {%0,%1,%2,%3}, [%4];"
                 : "=r"(r[0]), "=r"(r[1]), "=r"(r[2]), "=r"(r[3]) : "r"(a));
}
__device__ __forceinline__ void ldsm_x4t(u32* r, u32 a) {
    asm volatile("ldmatrix.sync.aligned.m8n8.x4.trans.shared.b16 {%0,%1,%2,%3}, [%4];"
                 : "=r"(r[0]), "=r"(r[1]), "=r"(r[2]), "=r"(r[3]) : "r"(a));
}
__device__ __forceinline__ void mma16816(float* d, const u32* a, u32 b0, u32 b1) {
    asm volatile(
        "mma.sync.aligned.m16n8k16.row.col.f32.f16.f16.f32 "
        "{%0,%1,%2,%3}, {%4,%5,%6,%7}, {%8,%9}, {%0,%1,%2,%3};"
        : "+f"(d[0]), "+f"(d[1]), "+f"(d[2]), "+f"(d[3])
        : "r"(a[0]), "r"(a[1]), "r"(a[2]), "r"(a[3]), "r"(b0), "r"(b1));
}
__device__ __forceinline__ u32 pack_h2(float a, float b) {
    __half2 h = __floats2half2_rn(a, b);
    return *reinterpret_cast<u32*>(&h);
}

// ---------------------------------------------------------------------------
// K1: per-row sum of exp(scores). HBM-roofline stream (512 MB, ~95% of spec).
// ---------------------------------------------------------------------------
__global__ void __launch_bounds__(256) k_rowsum(const float* __restrict__ scores) {
    int row  = blockIdx.x * 8 + threadIdx.y;
    int lane = threadIdx.x;
    const float4* p = (const float4*)(scores + (size_t)row * 2048);
    float z = 0.f;
#pragma unroll
    for (int i = 0; i < 16; i++) {
        float4 v = __ldcs(p + lane + i * 32);
        z += __expf(v.x) + __expf(v.y) + __expf(v.z) + __expf(v.w);
    }
#pragma unroll
    for (int o = 16; o; o >>= 1) z += __shfl_xor_sync(0xffffffffu, z, o);
    if (lane == 0) g_z1[row] = z;
}

// ---------------------------------------------------------------------------
// K2: causal second softmax + AV on tensor cores (fp16 single combo),
// software-pipelined double buffer, bulk-sync (2 CTAs/SM overlap phases).
// Grid (16, 32), 256 threads. l-tile 128, s-tile 64.
// ---------------------------------------------------------------------------
__global__ void __launch_bounds__(256, 2)
k_attn5(const float* __restrict__ scores,
        const float* __restrict__ values,
        float* __restrict__ out) {
    extern __shared__ __align__(16) char sm[];
    __shared__ float z2_s[128];

    const u32 smb = smem_u32(sm);
    int tid = threadIdx.x, wid = tid >> 5, lane = tid & 31;
    int bh = blockIdx.y, b = bh >> 4, h = bh & 15;
    int l0 = (15 - (int)blockIdx.x) * 128;   // heavy tiles first
    const int T = (l0 + 128) >> 6;           // s-tiles (2..32)

    // producer mapping: thread -> (row r, 32-col half of s-tile)
    const int r  = tid >> 1;
    const int c0 = (tid & 1) * 32;
    const int l  = l0 + r;
    const float rz1 = 1.0f / g_z1[bh * 2048 + l];
    const float* srow = scores + ((size_t)bh * 2048 + l) * 2048;
    const int vj = tid >> 2, vq = (tid & 3) * 16;
    const float* vrow = values + (size_t)b * 2048 * 1024 + h * 64 + vq;
    const u32 aOff = (u32)(r * PITCH + c0) * 2;
    const u32 vOff = V_OFF + (u32)(vj * PITCH + vq) * 2;

    // consumer mapping: warp -> rows 16w..16w+15, all 64 cols
    const int m0 = wid * 16;
    const int rowTop = l0 + m0 + 15;
    const u32 aLd = (u32)(((m0 + (lane & 15)) * PITCH + 8 * (lane >> 4)) * 2);
    const u32 bLd = V_OFF + (u32)(((lane & 15) * PITCH + 8 * (lane >> 4)) * 2);

    float acc[8][4];
#pragma unroll
    for (int n = 0; n < 8; n++)
#pragma unroll
        for (int q = 0; q < 4; q++) acc[n][q] = 0.f;
    float z2 = 0.f;

    // ---- producer compute+STS for one tile (data already in regs) ----
    auto produce = [&](int s0, const float4* s4, const float4* vv, char* buf) {
        u32 ap[16];
        if (s0 + c0 <= l) {
            const float* sf = (const float*)s4;
            if (s0 + c0 + 31 <= l) {            // full half: no per-elem mask
#pragma unroll
                for (int p = 0; p < 16; p++) {
                    float e0 = __expf(__expf(sf[2 * p])     * rz1);
                    float e1 = __expf(__expf(sf[2 * p + 1]) * rz1);
                    z2 += e0 + e1;
                    ap[p] = pack_h2(e0, e1);
                }
            } else {
#pragma unroll
                for (int p = 0; p < 16; p++) {
                    int j = s0 + c0 + 2 * p;
                    float e0 = (j     <= l) ? __expf(__expf(sf[2 * p])     * rz1) : 0.f;
                    float e1 = (j + 1 <= l) ? __expf(__expf(sf[2 * p + 1]) * rz1) : 0.f;
                    z2 += e0 + e1;
                    ap[p] = pack_h2(e0, e1);
                }
            }
        } else {
#pragma unroll
            for (int p = 0; p < 16; p++) ap[p] = 0u;
        }
#pragma unroll
        for (int g = 0; g < 4; g++)
            *(uint4*)(buf + aOff + 16 * g) =
                make_uint4(ap[4 * g], ap[4 * g + 1], ap[4 * g + 2], ap[4 * g + 3]);
        const float* f = (const float*)vv;
        u32 vp[8];
#pragma unroll
        for (int p = 0; p < 8; p++) vp[p] = pack_h2(f[2 * p], f[2 * p + 1]);
#pragma unroll
        for (int g = 0; g < 2; g++)
            *(uint4*)(buf + vOff + 16 * g) =
                make_uint4(vp[4 * g], vp[4 * g + 1], vp[4 * g + 2], vp[4 * g + 3]);
    };

    auto load_tile = [&](int s0, float4* s4, float4* vv) {
        const float4* vg = (const float4*)(vrow + (size_t)(s0 + vj) * 1024);
#pragma unroll
        for (int q = 0; q < 4; q++) vv[q] = __ldg(vg + q);
        if (s0 + c0 <= l) {
            const float4* spp = (const float4*)(srow + s0 + c0);
#pragma unroll
            for (int g = 0; g < 8; g++) s4[g] = __ldcs(spp + g);
        }
    };

    // ---- prologue: tile 0 ----
    {
        float4 s4[8], vv[4];
        load_tile(0, s4, vv);
        produce(0, s4, vv, sm);
    }

    for (int i = 0; i < T; i++) {
        int s0 = i * 64;
        __syncthreads();                        // STS(i) visible to all

        // prefetch tile i+1 (LDG latency hidden under MMA below)
        float4 s4[8], vv[4];
        if (i + 1 < T) load_tile(s0 + 64, s4, vv);

        // ---- MMA(i) ----
        if (s0 <= rowTop) {                     // skip fully-masked strips
            u32 base = smb + (i & 1) * STAGE;
#pragma unroll
            for (int k = 0; k < 4; k++) {
                u32 af[4];
                ldsm_x4(af, base + aLd + k * 32);
#pragma unroll
                for (int n = 0; n < 4; n++) {
                    u32 bf4[4];
                    ldsm_x4t(bf4, base + bLd + (u32)(k * 16 * PITCH * 2) + n * 32);
                    mma16816(acc[2 * n],     af, bf4[0], bf4[1]);
                    mma16816(acc[2 * n + 1], af, bf4[2], bf4[3]);
                }
            }
        }
        __syncthreads();                        // all MMA(i) done

        if (i + 1 < T)
            produce(s0 + 64, s4, vv, sm + ((i + 1) & 1) * STAGE);
    }

    // ---- Z2 reduce (two threads per row) ----
    float zo = __shfl_xor_sync(0xffffffffu, z2, 1);
    if ((tid & 1) == 0) z2_s[r] = z2 + zo;
    __syncthreads();

    // ---- epilogue: scale by 1/Z2, store [B,L,H,D] ----
    int r0 = m0 + (lane >> 2);
    float rz2a = 1.0f / z2_s[r0];
    float rz2b = 1.0f / z2_s[r0 + 8];
    float* o0 = out + (((size_t)b * 2048 + (l0 + r0))     * 16 + h) * 64 + (lane & 3) * 2;
    float* o1 = out + (((size_t)b * 2048 + (l0 + r0 + 8)) * 16 + h) * 64 + (lane & 3) * 2;
#pragma unroll
    for (int n = 0; n < 8; n++) {
        *(float2*)(o0 + n * 8) = make_float2(acc[n][0] * rz2a, acc[n][1] * rz2a);
        *(float2*)(o1 + n * 8) = make_float2(acc[n][2] * rz2b, acc[n][3] * rz2b);
    }
}

// ---------------------------------------------------------------------------
extern "C" void kernel_launch(void* const* d_in, const int* in_sizes, int n_in,
                              void* d_out, int out_size) {
    (void)in_sizes; (void)n_in; (void)out_size;
    const float* values = (const float*)d_in[2];
    const float* scores = (const float*)d_in[3];
    float* out = (float*)d_out;

    static int attr_done = 0;
    if (!attr_done) {
        cudaFuncSetAttribute(k_attn5, cudaFuncAttributeMaxDynamicSharedMemorySize, SMEM_TOT);
        attr_done = 1;
    }

    k_rowsum<<<dim3(NROWS / 8), dim3(32, 8)>>>(scores);
    k_attn5<<<dim3(16, 32), 256, SMEM_TOT>>>(scores, values, out);
}

// round 12
// speedup vs baseline: 1.6249x; 1.0161x over previous
#include <cuda_runtime.h>
#include <cuda_fp16.h>

typedef unsigned int u32;

// B=2, H=16, L=S=2048, E=D=64
// inputs: d_in[2]=values [B,S,H,D], d_in[3]=scores [B,H,L,S]; out [B,L,H,D] f32.
// Math: w=softmax(scores,-1); causal mask; A=softmax(w,-1); out=A@V.
//  * scores~N(0,1): first softmax safe without max subtraction.
//  * w in (0,1]: second softmax safe without max subtraction.
// K1: Z1[row]=sum exp(s).
// K2: e=exp(exp(s)/Z1) (causal), Z2=sum e (exact f32),
//     D = E @ V via fp16 mma.sync m16n8k16 (norm-level err ~3e-4 << 1e-3).
// R10 structure: warp-local fusion. Warp w produces AND consumes rows
// 16w..16w+15 of the l-tile -> A tile needs no CTA barrier (STS->ldsm is
// warp-local). Only the shared V tile needs one __syncthreads per s-tile.
// Causal skip applies to producer AND consumer (fully-masked strips do
// nothing). Z2 reduced via warp shuffles only.

#define NROWS (2 * 16 * 2048)
__device__ float g_z1[NROWS];

#define PITCH 72                       // fp16/row (144B, ldsm conflict-free)
#define V_OFF 18432                    // 128*72*2
#define STAGE 27648                    // + 64*72*2
#define SMEM_TOT (2 * STAGE)           // 55296

__device__ __forceinline__ u32 smem_u32(const void* p) {
    u32 a;
    asm("{ .reg .u64 t; cvta.to.shared.u64 t, %1; cvt.u32.u64 %0, t; }" : "=r"(a) : "l"(p));
    return a;
}
__device__ __forceinline__ void ldsm_x4(u32* r, u32 a) {
    asm volatile("ldmatrix.sync.aligned.m8n8.x4.shared.b16 {%0,%1,%2,%3}, [%4];"
                 : "=r"(r[0]), "=r"(r[1]), "=r"(r[2]), "=r"(r[3]) : "r"(a));
}
__device__ __forceinline__ void ldsm_x4t(u32* r, u32 a) {
    asm volatile("ldmatrix.sync.aligned.m8n8.x4.trans.shared.b16 {%0,%1,%2,%3}, [%4];"
                 : "=r"(r[0]), "=r"(r[1]), "=r"(r[2]), "=r"(r[3]) : "r"(a));
}
__device__ __forceinline__ void mma16816(float* d, const u32* a, u32 b0, u32 b1) {
    asm volatile(
        "mma.sync.aligned.m16n8k16.row.col.f32.f16.f16.f32 "
        "{%0,%1,%2,%3}, {%4,%5,%6,%7}, {%8,%9}, {%0,%1,%2,%3};"
        : "+f"(d[0]), "+f"(d[1]), "+f"(d[2]), "+f"(d[3])
        : "r"(a[0]), "r"(a[1]), "r"(a[2]), "r"(a[3]), "r"(b0), "r"(b1));
}
__device__ __forceinline__ u32 pack_h2(float a, float b) {
    __half2 h = __floats2half2_rn(a, b);
    return *reinterpret_cast<u32*>(&h);
}

// ---------------------------------------------------------------------------
// K1: per-row sum of exp(scores). HBM-roofline stream (512 MB).
// ---------------------------------------------------------------------------
__global__ void __launch_bounds__(256) k_rowsum(const float* __restrict__ scores) {
    int row  = blockIdx.x * 8 + threadIdx.y;
    int lane = threadIdx.x;
    const float4* p = (const float4*)(scores + (size_t)row * 2048);
    float z = 0.f;
#pragma unroll
    for (int i = 0; i < 16; i++) {
        float4 v = __ldcs(p + lane + i * 32);
        z += __expf(v.x) + __expf(v.y) + __expf(v.z) + __expf(v.w);
    }
#pragma unroll
    for (int o = 16; o; o >>= 1) z += __shfl_xor_sync(0xffffffffu, z, o);
    if (lane == 0) g_z1[row] = z;
}

// ---------------------------------------------------------------------------
// K2: warp-fused causal second softmax + AV on tensor cores (fp16).
// Grid (16, 32), 256 threads (8 warps x 16 rows). s-tile 64, double buffer,
// one __syncthreads per tile (guards shared V stage only).
// ---------------------------------------------------------------------------
__global__ void __launch_bounds__(256, 2)
k_attn6(const float* __restrict__ scores,
        const float* __restrict__ values,
        float* __restrict__ out) {
    extern __shared__ __align__(16) char sm[];

    const u32 smb = smem_u32(sm);
    int tid = threadIdx.x, wid = tid >> 5, lane = tid & 31;
    int bh = blockIdx.y, b = bh >> 4, h = bh & 15;
    int l0 = (15 - (int)blockIdx.x) * 128;   // heavy tiles first
    const int T = (l0 + 128) >> 6;           // s-tiles (2..32)

    const int m0 = wid * 16;                 // warp's row strip
    const int rowTop = l0 + m0 + 15;

    // producer mapping (warp-local): lane -> (row m0 + lane/2, 32-col half)
    const int r_l = lane >> 1;
    const int c0  = (lane & 1) * 32;
    const int l   = l0 + m0 + r_l;
    const float rz1 = 1.0f / g_z1[bh * 2048 + l];
    const float* srow = scores + ((size_t)bh * 2048 + l) * 2048;
    // V staging mapping (block-wide): thread -> (row tid/4, 16-col chunk)
    const int vj = tid >> 2, vq = (tid & 3) * 16;
    const float* vrow = values + (size_t)b * 2048 * 1024 + h * 64 + vq;

    const u32 aOff = (u32)((m0 + r_l) * PITCH + c0) * 2;
    const u32 vOff = V_OFF + (u32)(vj * PITCH + vq) * 2;
    const u32 aLd  = (u32)(((m0 + (lane & 15)) * PITCH + 8 * (lane >> 4)) * 2);
    const u32 bLd  = V_OFF + (u32)(((lane & 15) * PITCH + 8 * (lane >> 4)) * 2);

    float acc[8][4];
#pragma unroll
    for (int n = 0; n < 8; n++)
#pragma unroll
        for (int q = 0; q < 4; q++) acc[n][q] = 0.f;
    float z2 = 0.f;

    // ---- load tile i inputs into regs (scores only if strip active) ----
    auto load_tile = [&](int s0, float4* s4, float4* vv, bool act) {
        const float4* vg = (const float4*)(vrow + (size_t)(s0 + vj) * 1024);
#pragma unroll
        for (int q = 0; q < 4; q++) vv[q] = __ldg(vg + q);
        if (act && s0 + c0 <= l) {
            const float4* spp = (const float4*)(srow + s0 + c0);
#pragma unroll
            for (int g = 0; g < 8; g++) s4[g] = __ldcs(spp + g);
        }
    };

    // ---- exp/pack/STS for one tile (A warp-local, V shared) ----
    auto produce = [&](int s0, const float4* s4, const float4* vv, char* buf, bool act) {
        if (act) {
            u32 ap[16];
            if (s0 + c0 <= l) {
                const float* sf = (const float*)s4;
                if (s0 + c0 + 31 <= l) {            // full half: no mask
#pragma unroll
                    for (int p = 0; p < 16; p++) {
                        float e0 = __expf(__expf(sf[2 * p])     * rz1);
                        float e1 = __expf(__expf(sf[2 * p + 1]) * rz1);
                        z2 += e0 + e1;
                        ap[p] = pack_h2(e0, e1);
                    }
                } else {
#pragma unroll
                    for (int p = 0; p < 16; p++) {
                        int j = s0 + c0 + 2 * p;
                        float e0 = (j     <= l) ? __expf(__expf(sf[2 * p])     * rz1) : 0.f;
                        float e1 = (j + 1 <= l) ? __expf(__expf(sf[2 * p + 1]) * rz1) : 0.f;
                        z2 += e0 + e1;
                        ap[p] = pack_h2(e0, e1);
                    }
                }
            } else {
#pragma unroll
                for (int p = 0; p < 16; p++) ap[p] = 0u;
            }
#pragma unroll
            for (int g = 0; g < 4; g++)
                *(uint4*)(buf + aOff + 16 * g) =
                    make_uint4(ap[4 * g], ap[4 * g + 1], ap[4 * g + 2], ap[4 * g + 3]);
        }
        const float* f = (const float*)vv;
        u32 vp[8];
#pragma unroll
        for (int p = 0; p < 8; p++) vp[p] = pack_h2(f[2 * p], f[2 * p + 1]);
#pragma unroll
        for (int g = 0; g < 2; g++)
            *(uint4*)(buf + vOff + 16 * g) =
                make_uint4(vp[4 * g], vp[4 * g + 1], vp[4 * g + 2], vp[4 * g + 3]);
    };

    // ---- prologue: tile 0 (always active: s0=0 <= rowTop) ----
    {
        float4 s4[8], vv[4];
        load_tile(0, s4, vv, true);
        produce(0, s4, vv, sm, true);
    }
    __syncthreads();

    for (int i = 0; i < T; i++) {
        int s0 = i * 64;
        bool actNext = (i + 1 < T) && (s0 + 64 <= rowTop);
        bool haveNext = (i + 1 < T);

        // prefetch tile i+1 (hidden under MMA)
        float4 s4[8], vv[4];
        if (haveNext) load_tile(s0 + 64, s4, vv, actNext);

        // ---- MMA(i) on buf[i&1] (strip-active only) ----
        if (s0 <= rowTop) {
            u32 base = smb + (i & 1) * STAGE;
#pragma unroll
            for (int k = 0; k < 4; k++) {
                u32 af[4];
                ldsm_x4(af, base + aLd + k * 32);
#pragma unroll
                for (int n = 0; n < 4; n++) {
                    u32 bf4[4];
                    ldsm_x4t(bf4, base + bLd + (u32)(k * 16 * PITCH * 2) + n * 32);
                    mma16816(acc[2 * n],     af, bf4[0], bf4[1]);
                    mma16816(acc[2 * n + 1], af, bf4[2], bf4[3]);
                }
            }
        }

        // ---- produce tile i+1 into buf[(i+1)&1] ----
        if (haveNext)
            produce(s0 + 64, s4, vv, sm + ((i + 1) & 1) * STAGE, actNext);

        __syncthreads();   // V(i+1) visible; also spaces buffer reuse
    }

    // ---- Z2: warp-local pair reduce + shuffle broadcast ----
    z2 += __shfl_xor_sync(0xffffffffu, z2, 1);    // full row sum in lanes 2r,2r+1
    int q = lane >> 2;                             // 0..7
    float rz2a = 1.0f / __shfl_sync(0xffffffffu, z2, 2 * q);
    float rz2b = 1.0f / __shfl_sync(0xffffffffu, z2, 2 * (q + 8));

    // ---- epilogue: scale by 1/Z2, store [B,L,H,D] ----
    int r0 = m0 + q;
    float* o0 = out + (((size_t)b * 2048 + (l0 + r0))     * 16 + h) * 64 + (lane & 3) * 2;
    float* o1 = out + (((size_t)b * 2048 + (l0 + r0 + 8)) * 16 + h) * 64 + (lane & 3) * 2;
#pragma unroll
    for (int n = 0; n < 8; n++) {
        *(float2*)(o0 + n * 8) = make_float2(acc[n][0] * rz2a, acc[n][1] * rz2a);
        *(float2*)(o1 + n * 8) = make_float2(acc[n][2] * rz2b, acc[n][3] * rz2b);
    }
}

// ---------------------------------------------------------------------------
extern "C" void kernel_launch(void* const* d_in, const int* in_sizes, int n_in,
                              void* d_out, int out_size) {
    (void)in_sizes; (void)n_in; (void)out_size;
    const float* values = (const float*)d_in[2];
    const float* scores = (const float*)d_in[3];
    float* out = (float*)d_out;

    static int attr_done = 0;
    if (!attr_done) {
        cudaFuncSetAttribute(k_attn6, cudaFuncAttributeMaxDynamicSharedMemorySize, SMEM_TOT);
        attr_done = 1;
    }

    k_rowsum<<<dim3(NROWS / 8), dim3(32, 8)>>>(scores);
    k_attn6<<<dim3(16, 32), 256, SMEM_TOT>>>(scores, values, out);
}

// round 13
// speedup vs baseline: 1.8488x; 1.1378x over previous
#include <cuda_runtime.h>
#include <cuda_fp16.h>

typedef unsigned int u32;

// B=2, H=16, L=S=2048, E=D=64
// inputs: d_in[2]=values [B,S,H,D], d_in[3]=scores [B,H,L,S]; out [B,L,H,D] f32.
// Math: w=softmax(scores,-1); causal mask; A=softmax(w,-1); out=A@V.
//  * scores~N(0,1): first softmax safe without max subtraction.
//  * w in (0,1]: second softmax safe without max subtraction.
// K1: Z1[row]=sum exp(s).
// K2: e=exp(exp(s)/Z1) (causal), Z2=sum e (exact f32), D=E@V via fp16
//     mma.sync m16n8k16. R13: A-fragments built directly in REGISTERS
//     (gmem loads in fragment layout -> exp -> pack), no A smem at all;
//     only V staged in smem (double-buffered, 1 syncthreads/tile);
//     3 CTAs/SM via launch_bounds(256,3).

#define NROWS (2 * 16 * 2048)
__device__ float g_z1[NROWS];

#define PITCH 72                       // fp16/row for V (144B, ldsm conflict-free)
#define STAGE (64 * PITCH * 2)         // 9216 B
#define SMEM_TOT (2 * STAGE)           // 18432 B

__device__ __forceinline__ u32 smem_u32(const void* p) {
    u32 a;
    asm("{ .reg .u64 t; cvta.to.shared.u64 t, %1; cvt.u32.u64 %0, t; }" : "=r"(a) : "l"(p));
    return a;
}
__device__ __forceinline__ void ldsm_x4t(u32* r, u32 a) {
    asm volatile("ldmatrix.sync.aligned.m8n8.x4.trans.shared.b16 {%0,%1,%2,%3}, [%4];"
                 : "=r"(r[0]), "=r"(r[1]), "=r"(r[2]), "=r"(r[3]) : "r"(a));
}
__device__ __forceinline__ void mma16816(float* d, const u32* a, u32 b0, u32 b1) {
    asm volatile(
        "mma.sync.aligned.m16n8k16.row.col.f32.f16.f16.f32 "
        "{%0,%1,%2,%3}, {%4,%5,%6,%7}, {%8,%9}, {%0,%1,%2,%3};"
        : "+f"(d[0]), "+f"(d[1]), "+f"(d[2]), "+f"(d[3])
        : "r"(a[0]), "r"(a[1]), "r"(a[2]), "r"(a[3]), "r"(b0), "r"(b1));
}
__device__ __forceinline__ u32 pack_h2(float a, float b) {
    __half2 h = __floats2half2_rn(a, b);
    return *reinterpret_cast<u32*>(&h);
}
__device__ __forceinline__ float ee(float x, float rz1) {   // exp(exp(x)/Z1)
    return __expf(__expf(x) * rz1);
}

// ---------------------------------------------------------------------------
// K1: per-row sum of exp(scores). HBM-roofline stream (512 MB).
// ---------------------------------------------------------------------------
__global__ void __launch_bounds__(256) k_rowsum(const float* __restrict__ scores) {
    int row  = blockIdx.x * 8 + threadIdx.y;
    int lane = threadIdx.x;
    const float4* p = (const float4*)(scores + (size_t)row * 2048);
    float z = 0.f;
#pragma unroll
    for (int i = 0; i < 16; i++) {
        float4 v = __ldcs(p + lane + i * 32);
        z += __expf(v.x) + __expf(v.y) + __expf(v.z) + __expf(v.w);
    }
#pragma unroll
    for (int o = 16; o; o >>= 1) z += __shfl_xor_sync(0xffffffffu, z, o);
    if (lane == 0) g_z1[row] = z;
}

// ---------------------------------------------------------------------------
// K2: causal second softmax + AV, A-fragments in registers.
// Grid (16, 32), 256 threads (8 warps x 16 rows). s-tile 64.
// ---------------------------------------------------------------------------
__global__ void __launch_bounds__(256, 3)
k_attn7(const float* __restrict__ scores,
        const float* __restrict__ values,
        float* __restrict__ out) {
    extern __shared__ __align__(16) char sm[];

    const u32 smb = smem_u32(sm);
    int tid = threadIdx.x, wid = tid >> 5, lane = tid & 31;
    int bh = blockIdx.y, b = bh >> 4, h = bh & 15;
    int l0 = (15 - (int)blockIdx.x) * 128;   // heavy tiles first
    const int T = (l0 + 128) >> 6;           // s-tiles (2..32)

    const int m0 = wid * 16;                 // warp's row strip
    const int rowTop = l0 + m0 + 15;

    // A-fragment mapping: lane -> quad column m, row r
    const int m = lane & 3, r = lane >> 2;
    const int lA = l0 + m0 + r;              // causal limit, fragment rows a0/a2
    const int lB = lA + 8;                   //                fragment rows a1/a3
    const float rz1A = 1.0f / g_z1[bh * 2048 + lA];
    const float rz1B = 1.0f / g_z1[bh * 2048 + lB];
    const float* sA = scores + ((size_t)bh * 2048 + lA) * 2048 + 2 * m;
    const float* sB = sA + 8 * 2048;

    // V staging: thread -> (row vj, 16-col chunk)
    const int vj = tid >> 2, vq = (tid & 3) * 16;
    const float* vrow = values + (size_t)b * 2048 * 1024 + h * 64 + vq;
    const u32 vOff = (u32)(vj * PITCH + vq) * 2;
    const u32 bLd  = (u32)(((lane & 15) * PITCH + 8 * (lane >> 4)) * 2);

    float acc[8][4];
#pragma unroll
    for (int n = 0; n < 8; n++)
#pragma unroll
        for (int q = 0; q < 4; q++) acc[n][q] = 0.f;
    float zA = 0.f, zB = 0.f;
    u32 afr[16];                             // A fragments for current tile

    // ---- stage V tile (block-wide) ----
    auto stageV = [&](int s0, char* buf) {
        const float4* vg = (const float4*)(vrow + (size_t)(s0 + vj) * 1024);
        float4 vv[4];
#pragma unroll
        for (int q = 0; q < 4; q++) vv[q] = __ldg(vg + q);
        const float* f = (const float*)vv;
        u32 vp[8];
#pragma unroll
        for (int p = 0; p < 8; p++) vp[p] = pack_h2(f[2 * p], f[2 * p + 1]);
        *(uint4*)(buf + vOff)      = make_uint4(vp[0], vp[1], vp[2], vp[3]);
        *(uint4*)(buf + vOff + 16) = make_uint4(vp[4], vp[5], vp[6], vp[7]);
    };

    // ---- build A fragments in registers: LDG (frag layout) -> exp -> pack ----
    auto produceA = [&](int s0) {
        bool full = (s0 + 63 <= l0 + m0);    // no masking anywhere in warp
#pragma unroll
        for (int half = 0; half < 2; half++) {
            float2 raw[8];
#pragma unroll
            for (int kk = 0; kk < 2; kk++) {
                int c = s0 + 16 * (half * 2 + kk);
                raw[kk * 4 + 0] = __ldcs((const float2*)(sA + c));
                raw[kk * 4 + 1] = __ldcs((const float2*)(sB + c));
                raw[kk * 4 + 2] = __ldcs((const float2*)(sA + c + 8));
                raw[kk * 4 + 3] = __ldcs((const float2*)(sB + c + 8));
            }
#pragma unroll
            for (int kk = 0; kk < 2; kk++) {
                int k = half * 2 + kk;
                float eA0, eA1, eA8, eA9, eB0, eB1, eB8, eB9;
                if (full) {
                    eA0 = ee(raw[kk * 4 + 0].x, rz1A); eA1 = ee(raw[kk * 4 + 0].y, rz1A);
                    eB0 = ee(raw[kk * 4 + 1].x, rz1B); eB1 = ee(raw[kk * 4 + 1].y, rz1B);
                    eA8 = ee(raw[kk * 4 + 2].x, rz1A); eA9 = ee(raw[kk * 4 + 2].y, rz1A);
                    eB8 = ee(raw[kk * 4 + 3].x, rz1B); eB9 = ee(raw[kk * 4 + 3].y, rz1B);
                } else {
                    int c0 = s0 + 16 * k + 2 * m, c8 = c0 + 8;
                    eA0 = (c0     <= lA) ? ee(raw[kk * 4 + 0].x, rz1A) : 0.f;
                    eA1 = (c0 + 1 <= lA) ? ee(raw[kk * 4 + 0].y, rz1A) : 0.f;
                    eB0 = (c0     <= lB) ? ee(raw[kk * 4 + 1].x, rz1B) : 0.f;
                    eB1 = (c0 + 1 <= lB) ? ee(raw[kk * 4 + 1].y, rz1B) : 0.f;
                    eA8 = (c8     <= lA) ? ee(raw[kk * 4 + 2].x, rz1A) : 0.f;
                    eA9 = (c8 + 1 <= lA) ? ee(raw[kk * 4 + 2].y, rz1A) : 0.f;
                    eB8 = (c8     <= lB) ? ee(raw[kk * 4 + 3].x, rz1B) : 0.f;
                    eB9 = (c8 + 1 <= lB) ? ee(raw[kk * 4 + 3].y, rz1B) : 0.f;
                }
                zA += (eA0 + eA1) + (eA8 + eA9);
                zB += (eB0 + eB1) + (eB8 + eB9);
                afr[k * 4 + 0] = pack_h2(eA0, eA1);
                afr[k * 4 + 1] = pack_h2(eB0, eB1);
                afr[k * 4 + 2] = pack_h2(eA8, eA9);
                afr[k * 4 + 3] = pack_h2(eB8, eB9);
            }
        }
    };

    // ---- prologue: tile 0 (every strip active at s0=0) ----
    stageV(0, sm);
    produceA(0);
    __syncthreads();

    for (int i = 0; i < T; i++) {
        int s0 = i * 64;

        // ---- MMA(i): A from regs, B (V) from smem ----
        if (s0 <= rowTop) {
            u32 base = smb + (i & 1) * STAGE;
#pragma unroll
            for (int k = 0; k < 4; k++) {
                const u32* a = afr + 4 * k;
#pragma unroll
                for (int n = 0; n < 4; n++) {
                    u32 bf[4];
                    ldsm_x4t(bf, base + bLd + (u32)(k * 16 * PITCH * 2) + n * 32);
                    mma16816(acc[2 * n],     a, bf[0], bf[1]);
                    mma16816(acc[2 * n + 1], a, bf[2], bf[3]);
                }
            }
        }

        // ---- prepare tile i+1 ----
        if (i + 1 < T) {
            stageV(s0 + 64, sm + ((i + 1) & 1) * STAGE);
            if (s0 + 64 <= rowTop) produceA(s0 + 64);
        }
        __syncthreads();     // V(i+1) visible; buffer reuse spaced
    }

    // ---- Z2: quad reduce (cols of one row live in a quad) ----
    zA += __shfl_xor_sync(0xffffffffu, zA, 1);
    zA += __shfl_xor_sync(0xffffffffu, zA, 2);
    zB += __shfl_xor_sync(0xffffffffu, zB, 1);
    zB += __shfl_xor_sync(0xffffffffu, zB, 2);
    float rz2a = 1.0f / zA;
    float rz2b = 1.0f / zB;

    // ---- epilogue: scale by 1/Z2, store [B,L,H,D] ----
    float* o0 = out + (((size_t)b * 2048 + lA) * 16 + h) * 64 + 2 * m;
    float* o1 = out + (((size_t)b * 2048 + lB) * 16 + h) * 64 + 2 * m;
#pragma unroll
    for (int n = 0; n < 8; n++) {
        *(float2*)(o0 + n * 8) = make_float2(acc[n][0] * rz2a, acc[n][1] * rz2a);
        *(float2*)(o1 + n * 8) = make_float2(acc[n][2] * rz2b, acc[n][3] * rz2b);
    }
}

// ---------------------------------------------------------------------------
extern "C" void kernel_launch(void* const* d_in, const int* in_sizes, int n_in,
                              void* d_out, int out_size) {
    (void)in_sizes; (void)n_in; (void)out_size;
    const float* values = (const float*)d_in[2];
    const float* scores = (const float*)d_in[3];
    float* out = (float*)d_out;

    k_rowsum<<<dim3(NROWS / 8), dim3(32, 8)>>>(scores);
    k_attn7<<<dim3(16, 32), 256, SMEM_TOT>>>(scores, values, out);
}

// round 15
// speedup vs baseline: 1.9388x; 1.0487x over previous
#include <cuda_runtime.h>
#include <cuda_fp16.h>

typedef unsigned int u32;

// B=2, H=16, L=S=2048, E=D=64
// inputs: d_in[2]=values [B,S,H,D], d_in[3]=scores [B,H,L,S]; out [B,L,H,D] f32.
// Math: w=softmax(scores,-1); causal mask; A=softmax(w,-1); out=A@V.
//  * scores~N(0,1): first softmax safe without max subtraction.
//  * w in (0,1]: second softmax safe without max subtraction.
// K1: Z1[row]=sum exp(s).
// K2: e=exp(exp(s)/Z1) (causal), Z2=sum e (exact f32), D=E@V via fp16
//     mma.sync m16n8k16. A-fragments built directly in registers (no A smem);
//     V double-buffered in smem; 3 CTAs/SM. R14: prefetch.global.L2 for the
//     next tile's scores+V issued before MMA(i) so the post-MMA produce phase
//     hits L2 instead of DRAM.

#define NROWS (2 * 16 * 2048)
__device__ float g_z1[NROWS];

#define PITCH 72                       // fp16/row for V (144B, ldsm conflict-free)
#define STAGE (64 * PITCH * 2)         // 9216 B
#define SMEM_TOT (2 * STAGE)           // 18432 B

__device__ __forceinline__ u32 smem_u32(const void* p) {
    u32 a;
    asm("{ .reg .u64 t; cvta.to.shared.u64 t, %1; cvt.u32.u64 %0, t; }" : "=r"(a) : "l"(p));
    return a;
}
__device__ __forceinline__ void ldsm_x4t(u32* r, u32 a) {
    asm volatile("ldmatrix.sync.aligned.m8n8.x4.trans.shared.b16 {%0,%1,%2,%3}, [%4];"
                 : "=r"(r[0]), "=r"(r[1]), "=r"(r[2]), "=r"(r[3]) : "r"(a));
}
__device__ __forceinline__ void mma16816(float* d, const u32* a, u32 b0, u32 b1) {
    asm volatile(
        "mma.sync.aligned.m16n8k16.row.col.f32.f16.f16.f32 "
        "{%0,%1,%2,%3}, {%4,%5,%6,%7}, {%8,%9}, {%0,%1,%2,%3};"
        : "+f"(d[0]), "+f"(d[1]), "+f"(d[2]), "+f"(d[3])
        : "r"(a[0]), "r"(a[1]), "r"(a[2]), "r"(a[3]), "r"(b0), "r"(b1));
}
__device__ __forceinline__ u32 pack_h2(float a, float b) {
    __half2 h = __floats2half2_rn(a, b);
    return *reinterpret_cast<u32*>(&h);
}
__device__ __forceinline__ float ee(float x, float rz1) {   // exp(exp(x)/Z1)
    return __expf(__expf(x) * rz1);
}
__device__ __forceinline__ void pf_l2(const void* p) {
    asm volatile("prefetch.global.L2 [%0];" :: "l"(p));
}

// ---------------------------------------------------------------------------
// K1: per-row sum of exp(scores). HBM-roofline stream (512 MB).
// ---------------------------------------------------------------------------
__global__ void __launch_bounds__(256) k_rowsum(const float* __restrict__ scores) {
    int row  = blockIdx.x * 8 + threadIdx.y;
    int lane = threadIdx.x;
    const float4* p = (const float4*)(scores + (size_t)row * 2048);
    float z = 0.f;
#pragma unroll
    for (int i = 0; i < 16; i++) {
        float4 v = __ldcs(p + lane + i * 32);
        z += __expf(v.x) + __expf(v.y) + __expf(v.z) + __expf(v.w);
    }
#pragma unroll
    for (int o = 16; o; o >>= 1) z += __shfl_xor_sync(0xffffffffu, z, o);
    if (lane == 0) g_z1[row] = z;
}

// ---------------------------------------------------------------------------
// K2: causal second softmax + AV, A-fragments in registers, L2 prefetch.
// Grid (16, 32), 256 threads (8 warps x 16 rows). s-tile 64.
// ---------------------------------------------------------------------------
__global__ void __launch_bounds__(256, 3)
k_attn8(const float* __restrict__ scores,
        const float* __restrict__ values,
        float* __restrict__ out) {
    extern __shared__ __align__(16) char sm[];

    const u32 smb = smem_u32(sm);
    int tid = threadIdx.x, wid = tid >> 5, lane = tid & 31;
    int bh = blockIdx.y, b = bh >> 4, h = bh & 15;
    int l0 = (15 - (int)blockIdx.x) * 128;   // heavy tiles first
    const int T = (l0 + 128) >> 6;           // s-tiles (2..32)

    const int m0 = wid * 16;                 // warp's row strip
    const int rowTop = l0 + m0 + 15;

    // A-fragment mapping: lane -> quad column m, row r
    const int m = lane & 3, r = lane >> 2;
    const int lA = l0 + m0 + r;              // causal limit, fragment rows a0/a2
    const int lB = lA + 8;                   //                fragment rows a1/a3
    const float rz1A = 1.0f / g_z1[bh * 2048 + lA];
    const float rz1B = 1.0f / g_z1[bh * 2048 + lB];
    const float* sA = scores + ((size_t)bh * 2048 + lA) * 2048 + 2 * m;
    const float* sB = sA + 8 * 2048;
    // prefetch pointer: lane -> (row lane/2, 128B half-line)
    const float* sPf = scores + ((size_t)bh * 2048 + l0 + m0 + (lane >> 1)) * 2048
                     + (lane & 1) * 32;

    // V staging: thread -> (row vj, 16-col chunk)
    const int vj = tid >> 2, vq = (tid & 3) * 16;
    const float* vrow = values + (size_t)b * 2048 * 1024 + h * 64 + vq;
    const u32 vOff = (u32)(vj * PITCH + vq) * 2;
    const u32 bLd  = (u32)(((lane & 15) * PITCH + 8 * (lane >> 4)) * 2);
    const bool vPfT = ((tid & 1) == 0);      // threads owning a distinct 128B line

    float acc[8][4];
#pragma unroll
    for (int n = 0; n < 8; n++)
#pragma unroll
        for (int q = 0; q < 4; q++) acc[n][q] = 0.f;
    float zA = 0.f, zB = 0.f;
    u32 afr[16];                             // A fragments for current tile

    // ---- stage V tile (block-wide) ----
    auto stageV = [&](int s0, char* buf) {
        const float4* vg = (const float4*)(vrow + (size_t)(s0 + vj) * 1024);
        float4 vv[4];
#pragma unroll
        for (int q = 0; q < 4; q++) vv[q] = __ldg(vg + q);
        const float* f = (const float*)vv;
        u32 vp[8];
#pragma unroll
        for (int p = 0; p < 8; p++) vp[p] = pack_h2(f[2 * p], f[2 * p + 1]);
        *(uint4*)(buf + vOff)      = make_uint4(vp[0], vp[1], vp[2], vp[3]);
        *(uint4*)(buf + vOff + 16) = make_uint4(vp[4], vp[5], vp[6], vp[7]);
    };

    // ---- build A fragments in registers: LDG (frag layout) -> exp -> pack ----
    auto produceA = [&](int s0) {
        bool full = (s0 + 63 <= l0 + m0);    // no masking anywhere in warp
#pragma unroll
        for (int half = 0; half < 2; half++) {
            float2 raw[8];
#pragma unroll
            for (int kk = 0; kk < 2; kk++) {
                int c = s0 + 16 * (half * 2 + kk);
                raw[kk * 4 + 0] = __ldcs((const float2*)(sA + c));
                raw[kk * 4 + 1] = __ldcs((const float2*)(sB + c));
                raw[kk * 4 + 2] = __ldcs((const float2*)(sA + c + 8));
                raw[kk * 4 + 3] = __ldcs((const float2*)(sB + c + 8));
            }
#pragma unroll
            for (int kk = 0; kk < 2; kk++) {
                int k = half * 2 + kk;
                float eA0, eA1, eA8, eA9, eB0, eB1, eB8, eB9;
                if (full) {
                    eA0 = ee(raw[kk * 4 + 0].x, rz1A); eA1 = ee(raw[kk * 4 + 0].y, rz1A);
                    eB0 = ee(raw[kk * 4 + 1].x, rz1B); eB1 = ee(raw[kk * 4 + 1].y, rz1B);
                    eA8 = ee(raw[kk * 4 + 2].x, rz1A); eA9 = ee(raw[kk * 4 + 2].y, rz1A);
                    eB8 = ee(raw[kk * 4 + 3].x, rz1B); eB9 = ee(raw[kk * 4 + 3].y, rz1B);
                } else {
                    int c0 = s0 + 16 * k + 2 * m, c8 = c0 + 8;
                    eA0 = (c0     <= lA) ? ee(raw[kk * 4 + 0].x, rz1A) : 0.f;
                    eA1 = (c0 + 1 <= lA) ? ee(raw[kk * 4 + 0].y, rz1A) : 0.f;
                    eB0 = (c0     <= lB) ? ee(raw[kk * 4 + 1].x, rz1B) : 0.f;
                    eB1 = (c0 + 1 <= lB) ? ee(raw[kk * 4 + 1].y, rz1B) : 0.f;
                    eA8 = (c8     <= lA) ? ee(raw[kk * 4 + 2].x, rz1A) : 0.f;
                    eA9 = (c8 + 1 <= lA) ? ee(raw[kk * 4 + 2].y, rz1A) : 0.f;
                    eB8 = (c8     <= lB) ? ee(raw[kk * 4 + 3].x, rz1B) : 0.f;
                    eB9 = (c8 + 1 <= lB) ? ee(raw[kk * 4 + 3].y, rz1B) : 0.f;
                }
                zA += (eA0 + eA1) + (eA8 + eA9);
                zB += (eB0 + eB1) + (eB8 + eB9);
                afr[k * 4 + 0] = pack_h2(eA0, eA1);
                afr[k * 4 + 1] = pack_h2(eB0, eB1);
                afr[k * 4 + 2] = pack_h2(eA8, eA9);
                afr[k * 4 + 3] = pack_h2(eB8, eB9);
            }
        }
    };

    // ---- prologue: tile 0 (every strip active at s0=0) ----
    if (vPfT) pf_l2(vrow + (size_t)vj * 1024);
    pf_l2(sPf);
    stageV(0, sm);
    produceA(0);
    __syncthreads();

    for (int i = 0; i < T; i++) {
        int s0 = i * 64;
        bool haveNext = (i + 1 < T);
        bool actNext  = haveNext && (s0 + 64 <= rowTop);

        // ---- L2 prefetch for tile i+1 (hidden under MMA) ----
        if (actNext) pf_l2(sPf + s0 + 64);
        if (haveNext && vPfT) pf_l2(vrow + (size_t)(s0 + 64 + vj) * 1024);

        // ---- MMA(i): A from regs, B (V) from smem ----
        if (s0 <= rowTop) {
            u32 base = smb + (i & 1) * STAGE;
#pragma unroll
            for (int k = 0; k < 4; k++) {
                const u32* a = afr + 4 * k;
#pragma unroll
                for (int n = 0; n < 4; n++) {
                    u32 bf[4];
                    ldsm_x4t(bf, base + bLd + (u32)(k * 16 * PITCH * 2) + n * 32);
                    mma16816(acc[2 * n],     a, bf[0], bf[1]);
                    mma16816(acc[2 * n + 1], a, bf[2], bf[3]);
                }
            }
        }

        // ---- prepare tile i+1 (L2 hits thanks to prefetch) ----
        if (haveNext) {
            stageV(s0 + 64, sm + ((i + 1) & 1) * STAGE);
            if (actNext) produceA(s0 + 64);
        }
        __syncthreads();     // V(i+1) visible; buffer reuse spaced
    }

    // ---- Z2: quad reduce (cols of one row live in a quad) ----
    zA += __shfl_xor_sync(0xffffffffu, zA, 1);
    zA += __shfl_xor_sync(0xffffffffu, zA, 2);
    zB += __shfl_xor_sync(0xffffffffu, zB, 1);
    zB += __shfl_xor_sync(0xffffffffu, zB, 2);
    float rz2a = 1.0f / zA;
    float rz2b = 1.0f / zB;

    // ---- epilogue: scale by 1/Z2, store [B,L,H,D] ----
    float* o0 = out + (((size_t)b * 2048 + lA) * 16 + h) * 64 + 2 * m;
    float* o1 = out + (((size_t)b * 2048 + lB) * 16 + h) * 64 + 2 * m;
#pragma unroll
    for (int n = 0; n < 8; n++) {
        *(float2*)(o0 + n * 8) = make_float2(acc[n][0] * rz2a, acc[n][1] * rz2a);
        *(float2*)(o1 + n * 8) = make_float2(acc[n][2] * rz2b, acc[n][3] * rz2b);
    }
}

// ---------------------------------------------------------------------------
extern "C" void kernel_launch(void* const* d_in, const int* in_sizes, int n_in,
                              void* d_out, int out_size) {
    (void)in_sizes; (void)n_in; (void)out_size;
    const float* values = (const float*)d_in[2];
    const float* scores = (const float*)d_in[3];
    float* out = (float*)d_out;

    k_rowsum<<<dim3(NROWS / 8), dim3(32, 8)>>>(scores);
    k_attn8<<<dim3(16, 32), 256, SMEM_TOT>>>(scores, values, out);
}